// round 4
// baseline (speedup 1.0000x reference)
#include <cuda_runtime.h>
#include <cuda_bf16.h>
#include <mma.h>
#include <math.h>
#include <stdint.h>

using namespace nvcuda;

// Problem constants
#define NTOKS   65536
#define NGROUPS 8
#define SPER    8192
#define SWIN    128
#define NWIN    64
#define NKV     192
#define HEADS   8

// quantization scales
#define SC_ACT 16.0f     // LN outputs, attn out, h0
#define SC_H1  32.0f     // gelu outputs
#define SC_W   1024.0f   // all weights (|W| < 0.124)

// ---------------- device scratch ----------------
__device__ __align__(1024) __nv_bfloat16 g_q   [(size_t)NTOKS * 512];
__device__ __align__(1024) uint8_t       g_akv [(size_t)NTOKS * 512];
__device__ __align__(1024) __nv_bfloat16 g_kv  [(size_t)NTOKS * 1024];
__device__ __align__(1024) uint8_t       g_attn[(size_t)NTOKS * 512];
__device__ __align__(1024) float         g_x1  [(size_t)NTOKS * 512];
__device__ __align__(1024) uint8_t       g_h0  [(size_t)NTOKS * 512];
__device__ __align__(1024) uint8_t       g_h1  [(size_t)NTOKS * 1024];
__device__ __align__(1024) uint8_t       g_wkv [1024 * 512];
__device__ __align__(1024) uint8_t       g_wo  [512 * 512];
__device__ __align__(1024) uint8_t       g_wemb[512 * 512];
__device__ __align__(1024) uint8_t       g_w1  [1024 * 512];
__device__ __align__(1024) uint8_t       g_w2  [512 * 1024];

// ---------------- helpers ----------------
__device__ __forceinline__ uint32_t smem_u32(const void* p) {
    uint32_t a;
    asm("{ .reg .u64 t; cvta.to.shared.u64 t, %1; cvt.u32.u64 %0, t; }" : "=r"(a) : "l"(p));
    return a;
}
__device__ __forceinline__ void cp16_s(uint32_t daddr, const void* src) {
    asm volatile("cp.async.cg.shared.global [%0], [%1], 16;\n" :: "r"(daddr), "l"(src));
}
__device__ __forceinline__ void cp16(void* dst, const void* src) { cp16_s(smem_u32(dst), src); }
__device__ __forceinline__ void cp_commit() { asm volatile("cp.async.commit_group;\n"); }
template<int N> __device__ __forceinline__ void cp_wait() {
    asm volatile("cp.async.wait_group %0;\n" :: "n"(N));
}
__device__ __forceinline__ void ldsm4(uint32_t& r0, uint32_t& r1, uint32_t& r2, uint32_t& r3,
                                      uint32_t addr) {
    asm volatile("ldmatrix.sync.aligned.m8n8.x4.shared.b16 {%0,%1,%2,%3}, [%4];"
                 : "=r"(r0), "=r"(r1), "=r"(r2), "=r"(r3) : "r"(addr));
}
__device__ __forceinline__ void imma16832(int* d, const uint32_t* a, const uint32_t* b) {
    asm volatile("mma.sync.aligned.m16n8k32.row.col.s32.s8.s8.s32 "
                 "{%0,%1,%2,%3},{%4,%5,%6,%7},{%8,%9},{%0,%1,%2,%3};"
                 : "+r"(d[0]), "+r"(d[1]), "+r"(d[2]), "+r"(d[3])
                 : "r"(a[0]), "r"(a[1]), "r"(a[2]), "r"(a[3]), "r"(b[0]), "r"(b[1]));
}
__device__ __forceinline__ int q8(float v, float s) {
    int q = __float2int_rn(v * s);
    return max(-127, min(127, q));
}
__device__ __forceinline__ uint32_t pack4(int q0, int q1, int q2, int q3) {
    return (uint32_t)(q0 & 255) | ((uint32_t)(q1 & 255) << 8) |
           ((uint32_t)(q2 & 255) << 16) | ((uint32_t)(q3 & 255) << 24);
}

// ---------------- fused weight convert+transpose to int8 ----------------
__global__ void conv_w_all(const float* s0, uint8_t* d0,
                           const float* s1, uint8_t* d1,
                           const float* s2, uint8_t* d2,
                           const float* s3, uint8_t* d3,
                           const float* s4, uint8_t* d4) {
    int idx = blockIdx.x * blockDim.x + threadIdx.x;
    const float* src; uint8_t* dst; int K, Nout;
    switch (blockIdx.y) {
        case 0: src = s0; dst = d0; K = 512;  Nout = 1024; break;
        case 1: src = s1; dst = d1; K = 512;  Nout = 512;  break;
        case 2: src = s2; dst = d2; K = 512;  Nout = 512;  break;
        case 3: src = s3; dst = d3; K = 512;  Nout = 1024; break;
        default:src = s4; dst = d4; K = 1024; Nout = 512;  break;
    }
    if (idx < K * Nout) {
        int n = idx / K;
        int k = idx - n * K;
        dst[idx] = (uint8_t)(q8(src[k * Nout + n], SC_W) & 255);
    }
}

// ---------------- LayerNorm: optional bf16 out (o1) + optional int8 out (o2) ----------------
__global__ void __launch_bounds__(128)
ln_kernel(const float* __restrict__ x,
          const float* __restrict__ g1, const float* __restrict__ b1, __nv_bfloat16* __restrict__ o1,
          const float* __restrict__ g2, const float* __restrict__ b2, uint8_t* __restrict__ o2) {
    size_t t = blockIdx.x;
    int tid = threadIdx.x;
    float4 v = ((const float4*)(x + t * 512))[tid];
    float s = v.x + v.y + v.z + v.w;
    float q = v.x*v.x + v.y*v.y + v.z*v.z + v.w*v.w;
    for (int o = 16; o; o >>= 1) {
        s += __shfl_xor_sync(0xffffffffu, s, o);
        q += __shfl_xor_sync(0xffffffffu, q, o);
    }
    __shared__ float ss[4], sq[4];
    if ((tid & 31) == 0) { ss[tid >> 5] = s; sq[tid >> 5] = q; }
    __syncthreads();
    s = ss[0] + ss[1] + ss[2] + ss[3];
    q = sq[0] + sq[1] + sq[2] + sq[3];
    float mean = s * (1.0f / 512.0f);
    float var  = q * (1.0f / 512.0f) - mean * mean;
    float rstd = rsqrtf(var + 1e-5f);
    int c = tid * 4;
    float xh0 = (v.x - mean) * rstd;
    float xh1 = (v.y - mean) * rstd;
    float xh2 = (v.z - mean) * rstd;
    float xh3 = (v.w - mean) * rstd;
    if (o1) {
        float y0 = xh0 * g1[c]   + b1[c];
        float y1 = xh1 * g1[c+1] + b1[c+1];
        float y2 = xh2 * g1[c+2] + b1[c+2];
        float y3 = xh3 * g1[c+3] + b1[c+3];
        __nv_bfloat162* p = (__nv_bfloat162*)(o1 + t * 512 + c);
        p[0] = __floats2bfloat162_rn(y0, y1);
        p[1] = __floats2bfloat162_rn(y2, y3);
    }
    if (o2) {
        float y0 = xh0 * g2[c]   + b2[c];
        float y1 = xh1 * g2[c+1] + b2[c+1];
        float y2 = xh2 * g2[c+2] + b2[c+2];
        float y3 = xh3 * g2[c+3] + b2[c+3];
        *(uint32_t*)(o2 + t * 512 + c) =
            pack4(q8(y0, SC_ACT), q8(y1, SC_ACT), q8(y2, SC_ACT), q8(y3, SC_ACT));
    }
}

// ---------------- int8 IMMA GEMM: C[M,Nout] = A[M,KB] @ Bt[Nout,KB]^T ----------------
// 128x128 block tile, BK=128 bytes, 3-stage cp.async, XOR-swizzled smem, raw mma.sync.
enum { EPI_KV_BF16 = 0, EPI_I8 = 1, EPI_GELU_I8 = 2, EPI_RESID_F32 = 3 };

#define NST 3
#define STAGE_B 32768                       // 16KB A + 16KB B
#define GEMM_I8_SMEM (NST * STAGE_B)        // 98304

template<int KBYTES, int EPI>
__global__ void __launch_bounds__(256, 2)
gemm_i8(const uint8_t* __restrict__ A,
        const uint8_t* __restrict__ Bt,
        const float* __restrict__ bias, float inv, float oq,
        __nv_bfloat16* __restrict__ outB,
        uint8_t* __restrict__ outQ,
        float* __restrict__ outF,
        const float* __restrict__ resid,
        const float* __restrict__ scale,
        int Nout) {
    extern __shared__ __align__(1024) unsigned char dsm[];
    uint32_t smem_base = smem_u32(dsm);

    int tid  = threadIdx.x;
    int wid  = tid >> 5;
    int lane = tid & 31;
    int wm = wid & 3;      // 4 warps along M: 32 rows each
    int wn = wid >> 2;     // 2 warps along N: 64 cols each
    int mbase = blockIdx.y * 128;
    int nbase = blockIdx.x * 128;

    int d[2][8][4];
    #pragma unroll
    for (int i = 0; i < 2; i++)
        #pragma unroll
        for (int j = 0; j < 8; j++)
            #pragma unroll
            for (int k = 0; k < 4; k++) d[i][j][k] = 0;

    constexpr int KT = KBYTES / 128;

    // stage loader: tile = 128 rows x 8 chunks(16B); 256 thr x 4 chunks for A and B each
    auto load_stage = [&](int kt, int s) {
        uint32_t sa = smem_base + s * STAGE_B;
        uint32_t sb = sa + 16384;
        #pragma unroll
        for (int it = 0; it < 4; it++) {
            int ch  = tid + it * 256;
            int row = ch >> 3;
            int c   = ch & 7;
            int sw  = (c ^ (row & 7)) << 4;
            cp16_s(sa + row * 128 + sw, A  + (size_t)(mbase + row) * KBYTES + kt * 128 + c * 16);
            cp16_s(sb + row * 128 + sw, Bt + (size_t)(nbase + row) * KBYTES + kt * 128 + c * 16);
        }
    };

    #pragma unroll
    for (int p = 0; p < NST; p++) { load_stage(p, p); cp_commit(); }

    int rA = wm * 32 + (lane & 15);
    int rB = wn * 64 + (lane & 15);
    int hc = lane >> 4;

    for (int kt = 0; kt < KT; kt++) {
        cp_wait<NST - 1>();
        __syncthreads();
        int s = kt % NST;
        uint32_t sa = smem_base + s * STAGE_B;
        uint32_t sb = sa + 16384;
        #pragma unroll
        for (int ks = 0; ks < 4; ks++) {
            int c = ks * 2 + hc;
            uint32_t a[2][4];
            #pragma unroll
            for (int i = 0; i < 2; i++) {
                int row = rA + i * 16;
                ldsm4(a[i][0], a[i][1], a[i][2], a[i][3],
                      sa + row * 128 + (((c ^ (row & 7))) << 4));
            }
            uint32_t b[8][2];
            #pragma unroll
            for (int jj = 0; jj < 4; jj++) {
                int row = rB + jj * 16;
                uint32_t t0, t1, t2, t3;
                ldsm4(t0, t1, t2, t3, sb + row * 128 + (((c ^ (row & 7))) << 4));
                b[2*jj][0] = t0; b[2*jj][1] = t2;
                b[2*jj+1][0] = t1; b[2*jj+1][1] = t3;
            }
            #pragma unroll
            for (int i = 0; i < 2; i++)
                #pragma unroll
                for (int j = 0; j < 8; j++)
                    imma16832(d[i][j], a[i], b[j]);
        }
        __syncthreads();
        if (kt + NST < KT) load_stage(kt + NST, s);
        cp_commit();
    }

    // epilogue straight from registers
    int g   = lane >> 2;
    int tig = lane & 3;
    #pragma unroll
    for (int i = 0; i < 2; i++) {
        int gr0 = mbase + wm * 32 + i * 16 + g;
        #pragma unroll
        for (int j = 0; j < 8; j++) {
            int gc = nbase + wn * 64 + j * 8 + 2 * tig;
            float bz0 = bias[gc], bz1 = bias[gc + 1];
            float v0 = (float)d[i][j][0] * inv + bz0;
            float v1 = (float)d[i][j][1] * inv + bz1;
            float v2 = (float)d[i][j][2] * inv + bz0;
            float v3 = (float)d[i][j][3] * inv + bz1;
            if (EPI == EPI_KV_BF16) {
                *(__nv_bfloat162*)(outB + (size_t)gr0 * Nout + gc)       = __floats2bfloat162_rn(v0, v1);
                *(__nv_bfloat162*)(outB + (size_t)(gr0 + 8) * Nout + gc) = __floats2bfloat162_rn(v2, v3);
            } else if (EPI == EPI_I8 || EPI == EPI_GELU_I8) {
                if (EPI == EPI_GELU_I8) {
                    #pragma unroll
                    for (int q2 = 0; q2 < 1; q2++) { }
                    float u, th;
                    u = 0.7978845608028654f * (v0 + 0.044715f * v0 * v0 * v0);
                    asm("tanh.approx.f32 %0, %1;" : "=f"(th) : "f"(u)); v0 = 0.5f * v0 * (1.0f + th);
                    u = 0.7978845608028654f * (v1 + 0.044715f * v1 * v1 * v1);
                    asm("tanh.approx.f32 %0, %1;" : "=f"(th) : "f"(u)); v1 = 0.5f * v1 * (1.0f + th);
                    u = 0.7978845608028654f * (v2 + 0.044715f * v2 * v2 * v2);
                    asm("tanh.approx.f32 %0, %1;" : "=f"(th) : "f"(u)); v2 = 0.5f * v2 * (1.0f + th);
                    u = 0.7978845608028654f * (v3 + 0.044715f * v3 * v3 * v3);
                    asm("tanh.approx.f32 %0, %1;" : "=f"(th) : "f"(u)); v3 = 0.5f * v3 * (1.0f + th);
                }
                uint16_t p0 = (uint16_t)((q8(v0, oq) & 255) | ((q8(v1, oq) & 255) << 8));
                uint16_t p1 = (uint16_t)((q8(v2, oq) & 255) | ((q8(v3, oq) & 255) << 8));
                *(uint16_t*)(outQ + (size_t)gr0 * Nout + gc)       = p0;
                *(uint16_t*)(outQ + (size_t)(gr0 + 8) * Nout + gc) = p1;
            } else {  // EPI_RESID_F32
                float s0 = scale[gc], s1 = scale[gc + 1];
                const float2 r0 = *(const float2*)(resid + (size_t)gr0 * Nout + gc);
                const float2 r1 = *(const float2*)(resid + (size_t)(gr0 + 8) * Nout + gc);
                float2 o0, o1;
                o0.x = r0.x + s0 * v0; o0.y = r0.y + s1 * v1;
                o1.x = r1.x + s0 * v2; o1.y = r1.y + s1 * v3;
                *(float2*)(outF + (size_t)gr0 * Nout + gc)       = o0;
                *(float2*)(outF + (size_t)(gr0 + 8) * Nout + gc) = o1;
            }
        }
    }
}

// ---------------- windowed attention (round-2 core, int8 output) ----------------
#define LDQ 72
#define LDS_S 196
#define LDS_P 200
#define ATTN_SMEM (9216 + 27648 + 27648 + 50176)

__global__ void __launch_bounds__(256)
attn_kernel(const __nv_bfloat16* __restrict__ q,
            const __nv_bfloat16* __restrict__ kv,
            uint8_t* __restrict__ attn_out) {
    extern __shared__ __align__(16) unsigned char dsm[];
    __nv_bfloat16* sQ = (__nv_bfloat16*)dsm;
    __nv_bfloat16* sK = sQ + 64 * LDQ;
    __nv_bfloat16* sV = sK + NKV * LDQ;
    float*         sS = (float*)(dsm + 64512);
    __nv_bfloat16* sP = (__nv_bfloat16*)dsm;
    float*         sO = sS;

    int bid  = blockIdx.x;
    int head = bid & 7;
    int win  = bid >> 3;
    int g    = win >> 7;
    int sw   = win & 127;
    size_t tbase = (size_t)g * SPER + (size_t)sw * NWIN;

    int tid  = threadIdx.x;
    int warp = tid >> 5;
    bool valid0 = (sw > 0);
    bool valid2 = (sw < SWIN - 1);
    int cl0 = valid0 ? (sw - 1) : 0;
    int cl2 = valid2 ? (sw + 1) : (SWIN - 1);
    size_t kb0 = (size_t)g * SPER + (size_t)cl0 * NWIN;
    size_t kb2 = (size_t)g * SPER + (size_t)cl2 * NWIN;

    #pragma unroll
    for (int it = 0; it < 2; it++) {
        int ch = tid + it * 256;
        int r = ch >> 3, cc = (ch & 7) << 3;
        cp16(sQ + r * LDQ + cc, q + (tbase + r) * 512 + head * 64 + cc);
    }
    #pragma unroll
    for (int it = 0; it < 6; it++) {
        int ch = tid + it * 256;
        int r = ch >> 3, cc = (ch & 7) << 3;
        int nb = r >> 6, lr = r & 63;
        size_t tok = (nb == 0 ? kb0 : (nb == 1 ? tbase : kb2)) + lr;
        cp16(sK + r * LDQ + cc, kv + tok * 1024 + head * 64 + cc);
        cp16(sV + r * LDQ + cc, kv + tok * 1024 + 512 + head * 64 + cc);
    }
    cp_commit();
    cp_wait<0>();
    __syncthreads();

    {
        int r0 = (warp & 3) * 16;
        int c0 = (warp >> 2) * 96;
        wmma::fragment<wmma::matrix_a, 16, 16, 16, __nv_bfloat16, wmma::row_major> af[4];
        #pragma unroll
        for (int kk = 0; kk < 4; kk++)
            wmma::load_matrix_sync(af[kk], sQ + r0 * LDQ + kk * 16, LDQ);
        #pragma unroll
        for (int j = 0; j < 6; j++) {
            wmma::fragment<wmma::accumulator, 16, 16, 16, float> acc;
            wmma::fill_fragment(acc, 0.0f);
            #pragma unroll
            for (int kk = 0; kk < 4; kk++) {
                wmma::fragment<wmma::matrix_b, 16, 16, 16, __nv_bfloat16, wmma::col_major> bfr;
                wmma::load_matrix_sync(bfr, sK + (c0 + j * 16) * LDQ + kk * 16, LDQ);
                wmma::mma_sync(acc, af[kk], bfr, acc);
            }
            #pragma unroll
            for (int t2 = 0; t2 < acc.num_elements; t2++) acc.x[t2] *= 0.125f;
            wmma::store_matrix_sync(sS + r0 * LDS_S + c0 + j * 16, acc, LDS_S, wmma::mem_row_major);
        }
    }
    __syncthreads();

    {
        int r  = tid >> 2;
        int l4 = tid & 3;
        float* srow = sS + r * LDS_S;
        int lo = valid0 ? 0   : 64;
        int hi = valid2 ? 192 : 128;
        int cb = l4 * 48;
        float mx = -3.0e38f;
        #pragma unroll 8
        for (int c = cb; c < cb + 48; c++)
            if (c >= lo && c < hi) mx = fmaxf(mx, srow[c]);
        mx = fmaxf(mx, __shfl_xor_sync(0xffffffffu, mx, 1));
        mx = fmaxf(mx, __shfl_xor_sync(0xffffffffu, mx, 2));
        float sum = 0.0f;
        #pragma unroll 8
        for (int c = cb; c < cb + 48; c++) {
            float e = (c >= lo && c < hi) ? __expf(srow[c] - mx) : 0.0f;
            srow[c] = e;
            sum += e;
        }
        sum += __shfl_xor_sync(0xffffffffu, sum, 1);
        sum += __shfl_xor_sync(0xffffffffu, sum, 2);
        float inv = 1.0f / sum;
        __syncthreads();
        __nv_bfloat16* prow = sP + r * LDS_P;
        #pragma unroll 8
        for (int c = cb; c < cb + 48; c++)
            prow[c] = __float2bfloat16(srow[c] * inv);
    }
    __syncthreads();

    {
        int r0 = (warp & 3) * 16;
        int c0 = (warp >> 2) * 32;
        #pragma unroll
        for (int j = 0; j < 2; j++) {
            wmma::fragment<wmma::accumulator, 16, 16, 16, float> acc;
            wmma::fill_fragment(acc, 0.0f);
            #pragma unroll
            for (int kk = 0; kk < 12; kk++) {
                wmma::fragment<wmma::matrix_a, 16, 16, 16, __nv_bfloat16, wmma::row_major> afr;
                wmma::fragment<wmma::matrix_b, 16, 16, 16, __nv_bfloat16, wmma::row_major> bfr;
                wmma::load_matrix_sync(afr, sP + r0 * LDS_P + kk * 16, LDS_P);
                wmma::load_matrix_sync(bfr, sV + (kk * 16) * LDQ + c0 + j * 16, LDQ);
                wmma::mma_sync(acc, afr, bfr, acc);
            }
            wmma::store_matrix_sync(sO + r0 * LDQ + c0 + j * 16, acc, LDQ, wmma::mem_row_major);
        }
    }
    __syncthreads();

    // quantize O to int8 (scale 16), packed 4-byte stores
    #pragma unroll 2
    for (int e = tid; e < 64 * 16; e += 256) {
        int r = e >> 4, c4 = (e & 15) << 2;
        const float* o = sO + r * LDQ + c4;
        uint32_t pk = pack4(q8(o[0], SC_ACT), q8(o[1], SC_ACT),
                            q8(o[2], SC_ACT), q8(o[3], SC_ACT));
        *(uint32_t*)(attn_out + (tbase + r) * 512 + head * 64 + c4) = pk;
    }
}

// ---------------- host launcher ----------------
extern "C" void kernel_launch(void* const* d_in, const int* in_sizes, int n_in,
                              void* d_out, int out_size) {
    (void)in_sizes; (void)n_in; (void)out_size;
    const float* x       = (const float*)d_in[0];
    const float* ln_q_g  = (const float*)d_in[1];
    const float* ln_q_b  = (const float*)d_in[2];
    const float* ln_kv_g = (const float*)d_in[3];
    const float* ln_kv_b = (const float*)d_in[4];
    const float* W_kv    = (const float*)d_in[5];
    const float* b_kv    = (const float*)d_in[6];
    const float* W_o     = (const float*)d_in[7];
    const float* b_o     = (const float*)d_in[8];
    const float* gamma   = (const float*)d_in[9];
    const float* ln_m_g  = (const float*)d_in[10];
    const float* ln_m_b  = (const float*)d_in[11];
    const float* W_emb   = (const float*)d_in[12];
    const float* b_emb   = (const float*)d_in[13];
    const float* W1      = (const float*)d_in[14];
    const float* b1      = (const float*)d_in[15];
    const float* W2      = (const float*)d_in[16];
    const float* b2      = (const float*)d_in[17];
    const float* gamma_mlp = (const float*)d_in[18];
    float* out = (float*)d_out;

    void *p_q, *p_akv, *p_kv, *p_attn, *p_x1, *p_h0, *p_h1;
    void *p_wkv, *p_wo, *p_wemb, *p_w1, *p_w2;
    cudaGetSymbolAddress(&p_q,    g_q);
    cudaGetSymbolAddress(&p_akv,  g_akv);
    cudaGetSymbolAddress(&p_kv,   g_kv);
    cudaGetSymbolAddress(&p_attn, g_attn);
    cudaGetSymbolAddress(&p_x1,   g_x1);
    cudaGetSymbolAddress(&p_h0,   g_h0);
    cudaGetSymbolAddress(&p_h1,   g_h1);
    cudaGetSymbolAddress(&p_wkv,  g_wkv);
    cudaGetSymbolAddress(&p_wo,   g_wo);
    cudaGetSymbolAddress(&p_wemb, g_wemb);
    cudaGetSymbolAddress(&p_w1,   g_w1);
    cudaGetSymbolAddress(&p_w2,   g_w2);

    cudaFuncSetAttribute(attn_kernel, cudaFuncAttributeMaxDynamicSharedMemorySize, ATTN_SMEM);
    cudaFuncSetAttribute(gemm_i8<512,  EPI_KV_BF16>,  cudaFuncAttributeMaxDynamicSharedMemorySize, GEMM_I8_SMEM);
    cudaFuncSetAttribute(gemm_i8<512,  EPI_I8>,       cudaFuncAttributeMaxDynamicSharedMemorySize, GEMM_I8_SMEM);
    cudaFuncSetAttribute(gemm_i8<512,  EPI_GELU_I8>,  cudaFuncAttributeMaxDynamicSharedMemorySize, GEMM_I8_SMEM);
    cudaFuncSetAttribute(gemm_i8<512,  EPI_RESID_F32>,cudaFuncAttributeMaxDynamicSharedMemorySize, GEMM_I8_SMEM);
    cudaFuncSetAttribute(gemm_i8<1024, EPI_RESID_F32>,cudaFuncAttributeMaxDynamicSharedMemorySize, GEMM_I8_SMEM);

    const float INV_AW  = 1.0f / (SC_ACT * SC_W);
    const float INV_H1W = 1.0f / (SC_H1 * SC_W);

    // 0) weight convert+transpose -> int8
    conv_w_all<<<dim3(2048, 5), 256>>>(W_kv,  (uint8_t*)p_wkv,
                                       W_o,   (uint8_t*)p_wo,
                                       W_emb, (uint8_t*)p_wemb,
                                       W1,    (uint8_t*)p_w1,
                                       W2,    (uint8_t*)p_w2);

    // 1) dual LN: q (bf16) + akv (int8)
    ln_kernel<<<NTOKS, 128>>>(x, ln_q_g, ln_q_b, (__nv_bfloat16*)p_q,
                                 ln_kv_g, ln_kv_b, (uint8_t*)p_akv);

    // 2) kv = akv @ W_kv + b_kv -> bf16 [65536 x 1024]
    gemm_i8<512, EPI_KV_BF16><<<dim3(8, 512), 256, GEMM_I8_SMEM>>>(
        (const uint8_t*)p_akv, (const uint8_t*)p_wkv, b_kv, INV_AW, 0.0f,
        (__nv_bfloat16*)p_kv, nullptr, nullptr, nullptr, nullptr, 1024);

    // 3) windowed attention -> int8
    attn_kernel<<<NGROUPS * SWIN * HEADS, 256, ATTN_SMEM>>>(
        (const __nv_bfloat16*)p_q, (const __nv_bfloat16*)p_kv, (uint8_t*)p_attn);

    // 4) x1 = x + gamma * (attn @ W_o + b_o)
    gemm_i8<512, EPI_RESID_F32><<<dim3(4, 512), 256, GEMM_I8_SMEM>>>(
        (const uint8_t*)p_attn, (const uint8_t*)p_wo, b_o, INV_AW, 0.0f,
        nullptr, nullptr, (float*)p_x1, x, gamma, 512);

    // 5) aemb = LN_m(x1) -> int8
    ln_kernel<<<NTOKS, 128>>>((const float*)p_x1, nullptr, nullptr, nullptr,
                              ln_m_g, ln_m_b, (uint8_t*)p_akv);

    // 6) h0 = aemb @ W_emb + b_emb -> int8 (scale 16)
    gemm_i8<512, EPI_I8><<<dim3(4, 512), 256, GEMM_I8_SMEM>>>(
        (const uint8_t*)p_akv, (const uint8_t*)p_wemb, b_emb, INV_AW, SC_ACT,
        nullptr, (uint8_t*)p_h0, nullptr, nullptr, nullptr, 512);

    // 7) h1 = gelu(h0 @ W1 + b1) -> int8 (scale 32)
    gemm_i8<512, EPI_GELU_I8><<<dim3(8, 512), 256, GEMM_I8_SMEM>>>(
        (const uint8_t*)p_h0, (const uint8_t*)p_w1, b1, INV_AW, SC_H1,
        nullptr, (uint8_t*)p_h1, nullptr, nullptr, nullptr, 1024);

    // 8) out = x1 + gamma_mlp * (h1 @ W2 + b2)
    gemm_i8<1024, EPI_RESID_F32><<<dim3(4, 512), 256, GEMM_I8_SMEM>>>(
        (const uint8_t*)p_h1, (const uint8_t*)p_w2, b2, INV_H1W, 0.0f,
        nullptr, nullptr, out, (const float*)p_x1, gamma_mlp, 512);
}

// round 5
// speedup vs baseline: 1.7095x; 1.7095x over previous
#include <cuda_runtime.h>
#include <cuda_bf16.h>
#include <mma.h>
#include <math.h>
#include <stdint.h>

using namespace nvcuda;

// Problem constants
#define NTOKS   65536
#define NGROUPS 8
#define SPER    8192
#define SWIN    128
#define NWIN    64
#define NKV     192
#define HEADS   8

// ---------------- device scratch ----------------
__device__ __align__(1024) __nv_bfloat16 g_q   [(size_t)NTOKS * 512];
__device__ __align__(1024) __nv_bfloat16 g_akv [(size_t)NTOKS * 512];
__device__ __align__(1024) __nv_bfloat16 g_kv  [(size_t)NTOKS * 1024];
__device__ __align__(1024) __nv_bfloat16 g_attn[(size_t)NTOKS * 512];
__device__ __align__(1024) float         g_x1  [(size_t)NTOKS * 512];
__device__ __align__(1024) __nv_bfloat16 g_h1  [(size_t)NTOKS * 1024];
__device__ __align__(1024) __nv_bfloat16 g_wkv [1024 * 512];
__device__ __align__(1024) __nv_bfloat16 g_wo  [512 * 512];
__device__ __align__(1024) __nv_bfloat16 g_w1c [1024 * 512];   // (W_emb@W1)^T bf16
__device__ __align__(1024) __nv_bfloat16 g_w2  [512 * 1024];
__device__ __align__(1024) float         g_wcf32[512 * 1024];  // W_emb@W1 fp32
__device__ float g_bcomb[1024];

// ---------------- helpers ----------------
__device__ __forceinline__ uint32_t smem_u32(const void* p) {
    uint32_t a;
    asm("{ .reg .u64 t; cvta.to.shared.u64 t, %1; cvt.u32.u64 %0, t; }" : "=r"(a) : "l"(p));
    return a;
}
__device__ __forceinline__ void cp16_s(uint32_t daddr, const void* src) {
    asm volatile("cp.async.cg.shared.global [%0], [%1], 16;\n" :: "r"(daddr), "l"(src));
}
__device__ __forceinline__ void cp16(void* dst, const void* src) { cp16_s(smem_u32(dst), src); }
__device__ __forceinline__ void cp_commit() { asm volatile("cp.async.commit_group;\n"); }
template<int N> __device__ __forceinline__ void cp_wait() {
    asm volatile("cp.async.wait_group %0;\n" :: "n"(N));
}
__device__ __forceinline__ void ldsm4(uint32_t& r0, uint32_t& r1, uint32_t& r2, uint32_t& r3,
                                      uint32_t addr) {
    asm volatile("ldmatrix.sync.aligned.m8n8.x4.shared.b16 {%0,%1,%2,%3}, [%4];"
                 : "=r"(r0), "=r"(r1), "=r"(r2), "=r"(r3) : "r"(addr));
}
__device__ __forceinline__ void ldsm4t(uint32_t& r0, uint32_t& r1, uint32_t& r2, uint32_t& r3,
                                       uint32_t addr) {
    asm volatile("ldmatrix.sync.aligned.m8n8.x4.trans.shared.b16 {%0,%1,%2,%3}, [%4];"
                 : "=r"(r0), "=r"(r1), "=r"(r2), "=r"(r3) : "r"(addr));
}
__device__ __forceinline__ void hmma(float* d, const uint32_t* a, const uint32_t* b) {
    asm volatile("mma.sync.aligned.m16n8k16.row.col.f32.bf16.bf16.f32 "
                 "{%0,%1,%2,%3},{%4,%5,%6,%7},{%8,%9},{%0,%1,%2,%3};"
                 : "+f"(d[0]), "+f"(d[1]), "+f"(d[2]), "+f"(d[3])
                 : "r"(a[0]), "r"(a[1]), "r"(a[2]), "r"(a[3]), "r"(b[0]), "r"(b[1]));
}

// ---------------- W_comb = W_emb @ W1 (fp32 tiled) ----------------
__global__ void __launch_bounds__(256)
wcomb_kernel(const float* __restrict__ We, const float* __restrict__ W1, float* __restrict__ out) {
    __shared__ float sa[64][65];
    __shared__ float sb[64][65];
    int bi = blockIdx.y * 64, bn = blockIdx.x * 64;
    int tid = threadIdx.x;
    int ti = (tid >> 4) * 4, tn = (tid & 15) * 4;
    float acc[4][4] = {};
    for (int j0 = 0; j0 < 512; j0 += 64) {
        for (int t = tid; t < 4096; t += 256) {
            int r = t >> 6, c = t & 63;
            sa[r][c] = We[(size_t)(bi + r) * 512 + j0 + c];
            sb[r][c] = W1[(size_t)(j0 + r) * 1024 + bn + c];
        }
        __syncthreads();
        for (int j = 0; j < 64; j++) {
            float b0 = sb[j][tn], b1 = sb[j][tn + 1], b2 = sb[j][tn + 2], b3 = sb[j][tn + 3];
            #pragma unroll
            for (int i = 0; i < 4; i++) {
                float av = sa[ti + i][j];
                acc[i][0] += av * b0; acc[i][1] += av * b1;
                acc[i][2] += av * b2; acc[i][3] += av * b3;
            }
        }
        __syncthreads();
    }
    #pragma unroll
    for (int i = 0; i < 4; i++)
        #pragma unroll
        for (int n = 0; n < 4; n++)
            out[(size_t)(bi + ti + i) * 1024 + bn + tn + n] = acc[i][n];
}

// b_comb[n] = b1[n] + sum_j b_emb[j] * W1[j][n]
__global__ void bcomb_kernel(const float* __restrict__ b_emb, const float* __restrict__ W1,
                             const float* __restrict__ b1, float* __restrict__ out) {
    int n = blockIdx.x * 256 + threadIdx.x;
    if (n < 1024) {
        float acc = b1[n];
        for (int j = 0; j < 512; j++) acc += b_emb[j] * W1[j * 1024 + n];
        out[n] = acc;
    }
}

// ---------------- weight convert+transpose (4 segments) ----------------
__global__ void conv_w_all(const float* s0, __nv_bfloat16* d0,   // W_kv  512x1024
                           const float* s1, __nv_bfloat16* d1,   // W_o   512x512
                           const float* s2, __nv_bfloat16* d2,   // W_comb 512x1024
                           const float* s3, __nv_bfloat16* d3) { // W2   1024x512
    int idx = blockIdx.x * blockDim.x + threadIdx.x;
    const float* src; __nv_bfloat16* dst; int K, Nout;
    switch (blockIdx.y) {
        case 0: src = s0; dst = d0; K = 512;  Nout = 1024; break;
        case 1: src = s1; dst = d1; K = 512;  Nout = 512;  break;
        case 2: src = s2; dst = d2; K = 512;  Nout = 1024; break;
        default:src = s3; dst = d3; K = 1024; Nout = 512;  break;
    }
    if (idx < K * Nout) {
        int n = idx / K;
        int k = idx - n * K;
        dst[idx] = __float2bfloat16(src[k * Nout + n]);
    }
}

// ---------------- LayerNorm (optionally dual bf16 output) ----------------
__global__ void __launch_bounds__(128)
ln_kernel(const float* __restrict__ x,
          const float* __restrict__ g1, const float* __restrict__ b1, __nv_bfloat16* __restrict__ o1,
          const float* __restrict__ g2, const float* __restrict__ b2, __nv_bfloat16* __restrict__ o2) {
    size_t t = blockIdx.x;
    int tid = threadIdx.x;
    float4 v = ((const float4*)(x + t * 512))[tid];
    float s = v.x + v.y + v.z + v.w;
    float q = v.x*v.x + v.y*v.y + v.z*v.z + v.w*v.w;
    for (int o = 16; o; o >>= 1) {
        s += __shfl_xor_sync(0xffffffffu, s, o);
        q += __shfl_xor_sync(0xffffffffu, q, o);
    }
    __shared__ float ss[4], sq[4];
    if ((tid & 31) == 0) { ss[tid >> 5] = s; sq[tid >> 5] = q; }
    __syncthreads();
    s = ss[0] + ss[1] + ss[2] + ss[3];
    q = sq[0] + sq[1] + sq[2] + sq[3];
    float mean = s * (1.0f / 512.0f);
    float var  = q * (1.0f / 512.0f) - mean * mean;
    float rstd = rsqrtf(var + 1e-5f);
    int c = tid * 4;
    float xh0 = (v.x - mean) * rstd;
    float xh1 = (v.y - mean) * rstd;
    float xh2 = (v.z - mean) * rstd;
    float xh3 = (v.w - mean) * rstd;
    {
        float y0 = xh0 * g1[c]   + b1[c];
        float y1 = xh1 * g1[c+1] + b1[c+1];
        float y2 = xh2 * g1[c+2] + b1[c+2];
        float y3 = xh3 * g1[c+3] + b1[c+3];
        __nv_bfloat162* p = (__nv_bfloat162*)(o1 + t * 512 + c);
        p[0] = __floats2bfloat162_rn(y0, y1);
        p[1] = __floats2bfloat162_rn(y2, y3);
    }
    if (o2) {
        float y0 = xh0 * g2[c]   + b2[c];
        float y1 = xh1 * g2[c+1] + b2[c+1];
        float y2 = xh2 * g2[c+2] + b2[c+2];
        float y3 = xh3 * g2[c+3] + b2[c+3];
        __nv_bfloat162* p = (__nv_bfloat162*)(o2 + t * 512 + c);
        p[0] = __floats2bfloat162_rn(y0, y1);
        p[1] = __floats2bfloat162_rn(y2, y3);
    }
}

// ---------------- double-buffered WMMA GEMM (round-2, proven) ----------------
enum { EPI_BIAS_BF16 = 0, EPI_GELU_BF16 = 1, EPI_RESID_F32 = 2 };

#define BM2 128
#define BN2 128
#define BK2 64
#define LDT 72
#define TILE_B (BM2 * LDT * 2)
#define LDC2 132
#define GEMM_SMEM (4 * TILE_B)

template<int K, int EPI>
__global__ void __launch_bounds__(256)
gemm2(const __nv_bfloat16* __restrict__ A,
      const __nv_bfloat16* __restrict__ Bt,
      const float* __restrict__ bias,
      __nv_bfloat16* __restrict__ outB,
      float* __restrict__ outF,
      const float* __restrict__ resid,
      const float* __restrict__ scale,
      int Nout) {
    extern __shared__ __align__(16) unsigned char dsm[];
    __nv_bfloat16* sA[2] = {(__nv_bfloat16*)dsm, (__nv_bfloat16*)(dsm + TILE_B)};
    __nv_bfloat16* sB[2] = {(__nv_bfloat16*)(dsm + 2*TILE_B), (__nv_bfloat16*)(dsm + 3*TILE_B)};
    float* sC = (float*)dsm;

    int tid  = threadIdx.x;
    int warp = tid >> 5;
    int wm = warp & 3;
    int wn = warp >> 2;
    int mbase = blockIdx.y * BM2;
    int nbase = blockIdx.x * BN2;

    int r0c[4], c0c[4];
    #pragma unroll
    for (int it = 0; it < 4; it++) {
        int ch = tid + it * 256;
        r0c[it] = ch >> 3;
        c0c[it] = (ch & 7) << 3;
    }

    wmma::fragment<wmma::accumulator, 16, 16, 16, float> acc[2][4];
    #pragma unroll
    for (int i = 0; i < 2; i++)
        #pragma unroll
        for (int j = 0; j < 4; j++)
            wmma::fill_fragment(acc[i][j], 0.0f);

    constexpr int KT = K / BK2;

    #pragma unroll
    for (int p = 0; p < 2; p++) {
        #pragma unroll
        for (int it = 0; it < 4; it++)
            cp16(sA[p] + r0c[it] * LDT + c0c[it],
                 A + (size_t)(mbase + r0c[it]) * K + p * BK2 + c0c[it]);
        #pragma unroll
        for (int it = 0; it < 4; it++)
            cp16(sB[p] + r0c[it] * LDT + c0c[it],
                 Bt + (size_t)(nbase + r0c[it]) * K + p * BK2 + c0c[it]);
        cp_commit();
    }

    for (int kt = 0; kt < KT; kt++) {
        if (kt == KT - 1) cp_wait<0>(); else cp_wait<1>();
        __syncthreads();
        int b = kt & 1;
        #pragma unroll
        for (int ks = 0; ks < BK2; ks += 16) {
            wmma::fragment<wmma::matrix_a, 16, 16, 16, __nv_bfloat16, wmma::row_major> af[2];
            wmma::fragment<wmma::matrix_b, 16, 16, 16, __nv_bfloat16, wmma::col_major> bf[4];
            wmma::load_matrix_sync(af[0], sA[b] + (wm * 32)      * LDT + ks, LDT);
            wmma::load_matrix_sync(af[1], sA[b] + (wm * 32 + 16) * LDT + ks, LDT);
            #pragma unroll
            for (int j = 0; j < 4; j++)
                wmma::load_matrix_sync(bf[j], sB[b] + (wn * 64 + j * 16) * LDT + ks, LDT);
            #pragma unroll
            for (int i = 0; i < 2; i++)
                #pragma unroll
                for (int j = 0; j < 4; j++)
                    wmma::mma_sync(acc[i][j], af[i], bf[j], acc[i][j]);
        }
        __syncthreads();
        if (kt + 2 < KT) {
            #pragma unroll
            for (int it = 0; it < 4; it++)
                cp16(sA[b] + r0c[it] * LDT + c0c[it],
                     A + (size_t)(mbase + r0c[it]) * K + (kt + 2) * BK2 + c0c[it]);
            #pragma unroll
            for (int it = 0; it < 4; it++)
                cp16(sB[b] + r0c[it] * LDT + c0c[it],
                     Bt + (size_t)(nbase + r0c[it]) * K + (kt + 2) * BK2 + c0c[it]);
            cp_commit();
        }
    }

    #pragma unroll
    for (int i = 0; i < 2; i++)
        #pragma unroll
        for (int j = 0; j < 4; j++)
            wmma::store_matrix_sync(sC + (wm * 32 + i * 16) * LDC2 + wn * 64 + j * 16,
                                    acc[i][j], LDC2, wmma::mem_row_major);
    __syncthreads();

    #pragma unroll 4
    for (int e = tid; e < BM2 * BN2; e += 256) {
        int r = e >> 7;
        int c = e & 127;
        float v = sC[r * LDC2 + c];
        int gr = mbase + r;
        int gc = nbase + c;
        float bz = bias[gc];
        if (EPI == EPI_BIAS_BF16) {
            outB[(size_t)gr * Nout + gc] = __float2bfloat16(v + bz);
        } else if (EPI == EPI_GELU_BF16) {
            float t = v + bz;
            float u = 0.7978845608028654f * (t + 0.044715f * t * t * t);
            float th;
            asm("tanh.approx.f32 %0, %1;" : "=f"(th) : "f"(u));
            outB[(size_t)gr * Nout + gc] = __float2bfloat16(0.5f * t * (1.0f + th));
        } else {
            float t = v + bz;
            outF[(size_t)gr * Nout + gc] = resid[(size_t)gr * Nout + gc] + scale[gc] * t;
        }
    }
}

// ---------------- attention: register-softmax flash style ----------------
#define LDQ 72
#define ATTN2_SMEM ((64 + 192 + 192) * LDQ * 2)   // 64512 bytes

__global__ void __launch_bounds__(128)
attn2_kernel(const __nv_bfloat16* __restrict__ q,
             const __nv_bfloat16* __restrict__ kv,
             __nv_bfloat16* __restrict__ attn_out) {
    extern __shared__ __align__(16) unsigned char dsm[];
    __nv_bfloat16* sQ = (__nv_bfloat16*)dsm;
    __nv_bfloat16* sK = sQ + 64 * LDQ;
    __nv_bfloat16* sV = sK + NKV * LDQ;

    int bid  = blockIdx.x;
    int head = bid & 7;
    int win  = bid >> 3;
    int g8   = win >> 7;
    int sw   = win & 127;
    size_t tbase = (size_t)g8 * SPER + (size_t)sw * NWIN;

    int tid  = threadIdx.x;
    bool valid0 = (sw > 0);
    bool valid2 = (sw < SWIN - 1);
    int cl0 = valid0 ? (sw - 1) : 0;
    int cl2 = valid2 ? (sw + 1) : (SWIN - 1);
    size_t kb0 = (size_t)g8 * SPER + (size_t)cl0 * NWIN;
    size_t kb2 = (size_t)g8 * SPER + (size_t)cl2 * NWIN;

    // async loads: Q 512 chunks (4/thread), K & V 1536 chunks (12/thread each)
    #pragma unroll
    for (int it = 0; it < 4; it++) {
        int ch = tid + it * 128;
        int r = ch >> 3, cc = (ch & 7) << 3;
        cp16(sQ + r * LDQ + cc, q + (tbase + r) * 512 + head * 64 + cc);
    }
    #pragma unroll
    for (int it = 0; it < 12; it++) {
        int ch = tid + it * 128;
        int r = ch >> 3, cc = (ch & 7) << 3;
        int nb = r >> 6, lr2 = r & 63;
        size_t tok = (nb == 0 ? kb0 : (nb == 1 ? tbase : kb2)) + lr2;
        cp16(sK + r * LDQ + cc, kv + tok * 1024 + head * 64 + cc);
        cp16(sV + r * LDQ + cc, kv + tok * 1024 + 512 + head * 64 + cc);
    }
    cp_commit();
    cp_wait<0>();
    __syncthreads();

    int warp = tid >> 5;
    int lane = tid & 31;
    int g    = lane >> 2;     // 0..7
    int tig  = lane & 3;      // 0..3
    int lr   = lane & 7;
    int lm   = lane >> 3;     // matrix index for ldmatrix.x4
    int r0   = warp * 16;     // q-row block

    // Q A-frags: 4 k-chunks of 16, kept in registers the whole time
    uint32_t aq[4][4];
    #pragma unroll
    for (int kk = 0; kk < 4; kk++) {
        int row = r0 + lr + ((lm & 1) << 3);
        int col = kk * 16 + ((lm & 2) << 2);
        ldsm4(aq[kk][0], aq[kk][1], aq[kk][2], aq[kk][3], smem_u32(sQ + row * LDQ + col));
    }

    // S = Q @ K^T : 16 x 192 per warp, in 24 m16n8 acc frags
    float sc[24][4];
    #pragma unroll
    for (int j = 0; j < 24; j++) { sc[j][0]=0.f; sc[j][1]=0.f; sc[j][2]=0.f; sc[j][3]=0.f; }

    #pragma unroll
    for (int nb = 0; nb < 12; nb++) {
        #pragma unroll
        for (int kk = 0; kk < 4; kk++) {
            int row = nb * 16 + lr + ((lm & 2) << 2);
            int col = kk * 16 + ((lm & 1) << 3);
            uint32_t b4[4];
            ldsm4(b4[0], b4[1], b4[2], b4[3], smem_u32(sK + row * LDQ + col));
            hmma(sc[2 * nb],     aq[kk], &b4[0]);
            hmma(sc[2 * nb + 1], aq[kk], &b4[2]);
        }
    }

    // masked softmax in registers (rows g and g+8; scale 1/8 folded into exp)
    int lo = valid0 ? 0   : 64;
    int hi = valid2 ? 192 : 128;
    float mx0 = -3.0e38f, mx1 = -3.0e38f;
    #pragma unroll
    for (int j = 0; j < 24; j++) {
        int c0 = j * 8 + 2 * tig;
        if (c0 >= lo && c0 < hi) {
            mx0 = fmaxf(mx0, fmaxf(sc[j][0], sc[j][1]));
            mx1 = fmaxf(mx1, fmaxf(sc[j][2], sc[j][3]));
        }
    }
    mx0 = fmaxf(mx0, __shfl_xor_sync(0xffffffffu, mx0, 1));
    mx0 = fmaxf(mx0, __shfl_xor_sync(0xffffffffu, mx0, 2));
    mx1 = fmaxf(mx1, __shfl_xor_sync(0xffffffffu, mx1, 1));
    mx1 = fmaxf(mx1, __shfl_xor_sync(0xffffffffu, mx1, 2));

    float sum0 = 0.f, sum1 = 0.f;
    #pragma unroll
    for (int j = 0; j < 24; j++) {
        int c0 = j * 8 + 2 * tig;
        bool ok = (c0 >= lo) && (c0 < hi);
        float e0 = ok ? __expf((sc[j][0] - mx0) * 0.125f) : 0.f;
        float e1 = ok ? __expf((sc[j][1] - mx0) * 0.125f) : 0.f;
        float e2 = ok ? __expf((sc[j][2] - mx1) * 0.125f) : 0.f;
        float e3 = ok ? __expf((sc[j][3] - mx1) * 0.125f) : 0.f;
        sc[j][0] = e0; sc[j][1] = e1; sc[j][2] = e2; sc[j][3] = e3;
        sum0 += e0 + e1;
        sum1 += e2 + e3;
    }
    sum0 += __shfl_xor_sync(0xffffffffu, sum0, 1);
    sum0 += __shfl_xor_sync(0xffffffffu, sum0, 2);
    sum1 += __shfl_xor_sync(0xffffffffu, sum1, 1);
    sum1 += __shfl_xor_sync(0xffffffffu, sum1, 2);
    float inv0 = 1.0f / sum0;
    float inv1 = 1.0f / sum1;

    // O = P @ V : 16 x 64 per warp; P frags built from sc registers
    float oa[8][4];
    #pragma unroll
    for (int j = 0; j < 8; j++) { oa[j][0]=0.f; oa[j][1]=0.f; oa[j][2]=0.f; oa[j][3]=0.f; }

    #pragma unroll
    for (int kk2 = 0; kk2 < 12; kk2++) {
        uint32_t ap[4];
        __nv_bfloat162 t;
        t = __floats2bfloat162_rn(sc[2*kk2][0]   * inv0, sc[2*kk2][1]   * inv0); ap[0] = *(uint32_t*)&t;
        t = __floats2bfloat162_rn(sc[2*kk2][2]   * inv1, sc[2*kk2][3]   * inv1); ap[1] = *(uint32_t*)&t;
        t = __floats2bfloat162_rn(sc[2*kk2+1][0] * inv0, sc[2*kk2+1][1] * inv0); ap[2] = *(uint32_t*)&t;
        t = __floats2bfloat162_rn(sc[2*kk2+1][2] * inv1, sc[2*kk2+1][3] * inv1); ap[3] = *(uint32_t*)&t;
        #pragma unroll
        for (int nb2 = 0; nb2 < 4; nb2++) {
            int row = kk2 * 16 + lr + ((lm & 1) << 3);
            int col = nb2 * 16 + ((lm & 2) << 2);
            uint32_t b4[4];
            ldsm4t(b4[0], b4[1], b4[2], b4[3], smem_u32(sV + row * LDQ + col));
            hmma(oa[2 * nb2],     ap, &b4[0]);
            hmma(oa[2 * nb2 + 1], ap, &b4[2]);
        }
    }

    // store O straight from registers (bf16x2 per pair)
    size_t rowg = tbase + r0 + g;
    #pragma unroll
    for (int j2 = 0; j2 < 8; j2++) {
        __nv_bfloat162 w0 = __floats2bfloat162_rn(oa[j2][0], oa[j2][1]);
        __nv_bfloat162 w1 = __floats2bfloat162_rn(oa[j2][2], oa[j2][3]);
        *(__nv_bfloat162*)(attn_out + rowg * 512 + head * 64 + j2 * 8 + 2 * tig) = w0;
        *(__nv_bfloat162*)(attn_out + (rowg + 8) * 512 + head * 64 + j2 * 8 + 2 * tig) = w1;
    }
}

// ---------------- host launcher ----------------
extern "C" void kernel_launch(void* const* d_in, const int* in_sizes, int n_in,
                              void* d_out, int out_size) {
    (void)in_sizes; (void)n_in; (void)out_size;
    const float* x       = (const float*)d_in[0];
    const float* ln_q_g  = (const float*)d_in[1];
    const float* ln_q_b  = (const float*)d_in[2];
    const float* ln_kv_g = (const float*)d_in[3];
    const float* ln_kv_b = (const float*)d_in[4];
    const float* W_kv    = (const float*)d_in[5];
    const float* b_kv    = (const float*)d_in[6];
    const float* W_o     = (const float*)d_in[7];
    const float* b_o     = (const float*)d_in[8];
    const float* gamma   = (const float*)d_in[9];
    const float* ln_m_g  = (const float*)d_in[10];
    const float* ln_m_b  = (const float*)d_in[11];
    const float* W_emb   = (const float*)d_in[12];
    const float* b_emb   = (const float*)d_in[13];
    const float* W1      = (const float*)d_in[14];
    const float* b1      = (const float*)d_in[15];
    const float* W2      = (const float*)d_in[16];
    const float* b2      = (const float*)d_in[17];
    const float* gamma_mlp = (const float*)d_in[18];
    float* out = (float*)d_out;

    void *p_q, *p_akv, *p_kv, *p_attn, *p_x1, *p_h1;
    void *p_wkv, *p_wo, *p_w1c, *p_w2, *p_wcf, *p_bc;
    cudaGetSymbolAddress(&p_q,    g_q);
    cudaGetSymbolAddress(&p_akv,  g_akv);
    cudaGetSymbolAddress(&p_kv,   g_kv);
    cudaGetSymbolAddress(&p_attn, g_attn);
    cudaGetSymbolAddress(&p_x1,   g_x1);
    cudaGetSymbolAddress(&p_h1,   g_h1);
    cudaGetSymbolAddress(&p_wkv,  g_wkv);
    cudaGetSymbolAddress(&p_wo,   g_wo);
    cudaGetSymbolAddress(&p_w1c,  g_w1c);
    cudaGetSymbolAddress(&p_w2,   g_w2);
    cudaGetSymbolAddress(&p_wcf,  g_wcf32);
    cudaGetSymbolAddress(&p_bc,   g_bcomb);

    cudaFuncSetAttribute(attn2_kernel, cudaFuncAttributeMaxDynamicSharedMemorySize, ATTN2_SMEM);
    cudaFuncSetAttribute(gemm2<512,  EPI_BIAS_BF16>, cudaFuncAttributeMaxDynamicSharedMemorySize, GEMM_SMEM);
    cudaFuncSetAttribute(gemm2<512,  EPI_GELU_BF16>, cudaFuncAttributeMaxDynamicSharedMemorySize, GEMM_SMEM);
    cudaFuncSetAttribute(gemm2<512,  EPI_RESID_F32>, cudaFuncAttributeMaxDynamicSharedMemorySize, GEMM_SMEM);
    cudaFuncSetAttribute(gemm2<1024, EPI_RESID_F32>, cudaFuncAttributeMaxDynamicSharedMemorySize, GEMM_SMEM);

    // 0a) W_comb = W_emb @ W1 (fp32), b_comb
    wcomb_kernel<<<dim3(16, 8), 256>>>(W_emb, W1, (float*)p_wcf);
    bcomb_kernel<<<4, 256>>>(b_emb, W1, b1, (float*)p_bc);

    // 0b) weight convert+transpose (bf16, [Nout][K])
    conv_w_all<<<dim3(2048, 4), 256>>>(W_kv, (__nv_bfloat16*)p_wkv,
                                       W_o,  (__nv_bfloat16*)p_wo,
                                       (const float*)p_wcf, (__nv_bfloat16*)p_w1c,
                                       W2,   (__nv_bfloat16*)p_w2);

    // 1) dual LN
    ln_kernel<<<NTOKS, 128>>>(x, ln_q_g, ln_q_b, (__nv_bfloat16*)p_q,
                                 ln_kv_g, ln_kv_b, (__nv_bfloat16*)p_akv);

    // 2) kv = akv @ W_kv + b_kv
    gemm2<512, EPI_BIAS_BF16><<<dim3(1024 / BN2, NTOKS / BM2), 256, GEMM_SMEM>>>(
        (const __nv_bfloat16*)p_akv, (const __nv_bfloat16*)p_wkv, b_kv,
        (__nv_bfloat16*)p_kv, nullptr, nullptr, nullptr, 1024);

    // 3) windowed attention (register softmax)
    attn2_kernel<<<NGROUPS * SWIN * HEADS, 128, ATTN2_SMEM>>>(
        (const __nv_bfloat16*)p_q, (const __nv_bfloat16*)p_kv, (__nv_bfloat16*)p_attn);

    // 4) x1 = x + gamma * (attn @ W_o + b_o)
    gemm2<512, EPI_RESID_F32><<<dim3(512 / BN2, NTOKS / BM2), 256, GEMM_SMEM>>>(
        (const __nv_bfloat16*)p_attn, (const __nv_bfloat16*)p_wo, b_o,
        nullptr, (float*)p_x1, x, gamma, 512);

    // 5) aemb = LN_m(x1)
    ln_kernel<<<NTOKS, 128>>>((const float*)p_x1, ln_m_g, ln_m_b, (__nv_bfloat16*)p_akv,
                              nullptr, nullptr, nullptr);

    // 6) h1 = gelu(aemb @ W_comb + b_comb)   [fused emb+W1]
    gemm2<512, EPI_GELU_BF16><<<dim3(1024 / BN2, NTOKS / BM2), 256, GEMM_SMEM>>>(
        (const __nv_bfloat16*)p_akv, (const __nv_bfloat16*)p_w1c, (const float*)p_bc,
        (__nv_bfloat16*)p_h1, nullptr, nullptr, nullptr, 1024);

    // 7) out = x1 + gamma_mlp * (h1 @ W2 + b2)
    gemm2<1024, EPI_RESID_F32><<<dim3(512 / BN2, NTOKS / BM2), 256, GEMM_SMEM>>>(
        (const __nv_bfloat16*)p_h1, (const __nv_bfloat16*)p_w2, b2,
        nullptr, out, (const float*)p_x1, gamma_mlp, 512);
}